// round 6
// baseline (speedup 1.0000x reference)
#include <cuda_runtime.h>
#include <cuda_bf16.h>
#include <cstdint>

#define TT 16          // time steps
#define BB 16          // batch
#define CC 256         // channels C (and Cc)
#define DD 512         // 2*C
#define HW 1024        // H*W
#define NBLK 740       // 148 SMs x 5 CTAs -- all co-resident (launch_bounds)
#define NHEAD 256      // head blocks
#define NTILE (TT * BB * CC / 8)   // 8192 film tiles (8 channels each)

// Scratch / sync (no allocation allowed; zero-initialized at module load)
__device__ float g_params[TT * BB * DD];   // [T,B,2C]
__device__ int   g_done;                   // head-completion counter
__device__ int   g_exit;                   // block-exit counter (for reset)

// ---------------------------------------------------------------------------
// One fused persistent kernel.
//   Blocks 0..255   : LIF + GEMM head for (b = bid/16, d-range = (bid%16)*32)
//   Barrier         : spin until g_done == 256 (all blocks resident -> safe)
//   All 740 blocks  : grid-stride FiLM over 8192 tiles (8 channels/tile),
//                     body identical to the measured 77us / 6.3TB/s kernel.
//   Counters self-reset via g_exit so every graph replay starts from 0.
// ---------------------------------------------------------------------------
__global__ void __launch_bounds__(256, 5) fused_kernel(
    const float4* __restrict__ x,
    const float*  __restrict__ cond,
    const float*  __restrict__ Wm,
    const float*  __restrict__ bias,
    float4*       __restrict__ out) {
    __shared__ float s_sp[TT][CC + 4];     // +4 pad: kills LDS bank conflicts
    int tid = threadIdx.x;
    int bid = blockIdx.x;

    if (bid < NHEAD) {
        int b     = bid >> 4;
        int dbase = (bid & 15) << 5;       // 32 d's per head block

        // --- LIF scan: one thread per cc, loads hoisted (MLP=16) ---
        {
            int cc = tid;
            float xv[TT];
#pragma unroll
            for (int t = 0; t < TT; ++t)
                xv[t] = cond[(t * BB + b) * CC + cc];
            float v = 0.0f;
#pragma unroll
            for (int t = 0; t < TT; ++t) {
                v = v + (xv[t] - v) * 0.5f;              // charge (TAU=2)
                float s = (v >= 1.0f) ? 1.0f : 0.0f;     // fire
                s_sp[t][cc] = s;
                v = (1.0f - s) * v;                      // hard reset
            }
        }
        __syncthreads();

        // --- GEMM: thread-per-(d, t-pair). W read as float4 in native
        //     layout (4 rows/warp, broadcast within 8-lane groups). ---
        int dl = tid >> 3;                 // 0..31
        int tp = tid & 7;                  // 0..7 -> t pair (2tp, 2tp+1)
        int d  = dbase + dl;
        int t0 = tp * 2, t1 = t0 + 1;

        const float4* __restrict__ w4 = (const float4*)(Wm + (size_t)d * CC);
        const float4* __restrict__ s0 = (const float4*)&s_sp[t0][0];
        const float4* __restrict__ s1 = (const float4*)&s_sp[t1][0];

        float a0 = bias[d], a1 = a0;
#pragma unroll 8
        for (int k = 0; k < CC / 4; ++k) {
            float4 w = w4[k];
            float4 p = s0[k];
            float4 q = s1[k];
            a0 = fmaf(p.x, w.x, a0); a0 = fmaf(p.y, w.y, a0);
            a0 = fmaf(p.z, w.z, a0); a0 = fmaf(p.w, w.w, a0);
            a1 = fmaf(q.x, w.x, a1); a1 = fmaf(q.y, w.y, a1);
            a1 = fmaf(q.z, w.z, a1); a1 = fmaf(q.w, w.w, a1);
        }
        g_params[(t0 * BB + b) * DD + d] = a0;
        g_params[(t1 * BB + b) * DD + d] = a1;

        __threadfence();                   // make stores globally visible
        __syncthreads();
        if (tid == 0) atomicAdd(&g_done, 1);
    }

    // --- barrier: wait until all head blocks have published params ---
    if (tid == 0) {
        while (*(volatile int*)&g_done < NHEAD) __nanosleep(64);
    }
    __syncthreads();
    __threadfence();

    // --- FiLM: grid-stride over 8192 tiles, 8 channels per tile ---
    for (int tile = bid; tile < NTILE; tile += NBLK) {
        unsigned row0 = (unsigned)tile * 8;
        unsigned tb   = row0 >> 8;
        unsigned c0   = row0 & (CC - 1);

        size_t base = (size_t)row0 * 256 + tid;

        float4 v0 = x[base];
        float4 v1 = x[base + 256];
        float4 v2 = x[base + 512];
        float4 v3 = x[base + 768];
        float4 v4 = x[base + 1024];
        float4 v5 = x[base + 1280];
        float4 v6 = x[base + 1536];
        float4 v7 = x[base + 1792];

        const float4* __restrict__ p4 = (const float4*)(g_params + tb * DD + c0);
        float4 ga = p4[0];
        float4 gb = p4[1];
        float4 ba = p4[CC / 4];
        float4 bb = p4[CC / 4 + 1];

        float g0 = 1.0f + ga.x, g1 = 1.0f + ga.y;
        float g2 = 1.0f + ga.z, g3 = 1.0f + ga.w;
        float g4 = 1.0f + gb.x, g5 = 1.0f + gb.y;
        float g6 = 1.0f + gb.z, g7 = 1.0f + gb.w;

        float4 o;
        o.x = fmaf(g0, v0.x, ba.x); o.y = fmaf(g0, v0.y, ba.x);
        o.z = fmaf(g0, v0.z, ba.x); o.w = fmaf(g0, v0.w, ba.x);
        out[base] = o;
        o.x = fmaf(g1, v1.x, ba.y); o.y = fmaf(g1, v1.y, ba.y);
        o.z = fmaf(g1, v1.z, ba.y); o.w = fmaf(g1, v1.w, ba.y);
        out[base + 256] = o;
        o.x = fmaf(g2, v2.x, ba.z); o.y = fmaf(g2, v2.y, ba.z);
        o.z = fmaf(g2, v2.z, ba.z); o.w = fmaf(g2, v2.w, ba.z);
        out[base + 512] = o;
        o.x = fmaf(g3, v3.x, ba.w); o.y = fmaf(g3, v3.y, ba.w);
        o.z = fmaf(g3, v3.z, ba.w); o.w = fmaf(g3, v3.w, ba.w);
        out[base + 768] = o;
        o.x = fmaf(g4, v4.x, bb.x); o.y = fmaf(g4, v4.y, bb.x);
        o.z = fmaf(g4, v4.z, bb.x); o.w = fmaf(g4, v4.w, bb.x);
        out[base + 1024] = o;
        o.x = fmaf(g5, v5.x, bb.y); o.y = fmaf(g5, v5.y, bb.y);
        o.z = fmaf(g5, v5.z, bb.y); o.w = fmaf(g5, v5.w, bb.y);
        out[base + 1280] = o;
        o.x = fmaf(g6, v6.x, bb.z); o.y = fmaf(g6, v6.y, bb.z);
        o.z = fmaf(g6, v6.z, bb.z); o.w = fmaf(g6, v6.w, bb.z);
        out[base + 1536] = o;
        o.x = fmaf(g7, v7.x, bb.w); o.y = fmaf(g7, v7.y, bb.w);
        o.z = fmaf(g7, v7.z, bb.w); o.w = fmaf(g7, v7.w, bb.w);
        out[base + 1792] = o;
    }

    // --- reset counters for the next (graph-replayed) launch ---
    __syncthreads();
    if (tid == 0) {
        int e = atomicAdd(&g_exit, 1);
        if (e == NBLK - 1) {
            g_done = 0;
            g_exit = 0;
        }
    }
}

// ---------------------------------------------------------------------------
extern "C" void kernel_launch(void* const* d_in, const int* in_sizes, int n_in,
                              void* d_out, int out_size) {
    const float* x    = (const float*)d_in[0];   // [T,B,C,H,W]
    const float* cond = (const float*)d_in[1];   // [T,B,Cc]
    const float* Wm   = (const float*)d_in[2];   // [2C,Cc]
    const float* bias = (const float*)d_in[3];   // [2C]
    float* out = (float*)d_out;

    fused_kernel<<<NBLK, 256>>>((const float4*)x, cond, Wm, bias,
                                (float4*)out);
}

// round 7
// speedup vs baseline: 1.1693x; 1.1693x over previous
#include <cuda_runtime.h>
#include <cuda_bf16.h>
#include <cstdint>

#define TT 16          // time steps
#define BB 16          // batch
#define CC 256         // channels C (and Cc)
#define DD 512         // 2*C
#define HW 1024        // H*W

// Scratch (no allocation allowed)
__device__ float g_params[TT * BB * DD];   // [T,B,2C]

// ---------------------------------------------------------------------------
// Fused LIF+GEMM head. Grid: 256 blocks (16 b x 16 d-chunks) x 256 threads.
// Phase A: thread cc runs the LIF scan (16 hoisted cond loads -> register
//          recurrence), spikes -> padded smem.
// Phase B: thread = (dl 0..31, tp 0..7): d = dbase+dl, t-pair (2tp, 2tp+1).
//          W row d read as float4 in NATIVE layout (8-lane broadcast),
//          spikes read as float4 from smem. No shuffles, no transpose.
// ---------------------------------------------------------------------------
__global__ void __launch_bounds__(256) head_kernel(
    const float* __restrict__ cond,
    const float* __restrict__ Wm,
    const float* __restrict__ bias) {
    __shared__ float s_sp[TT][CC + 4];     // +4 pad
    int tid   = threadIdx.x;
    int b     = blockIdx.x >> 4;
    int dbase = (blockIdx.x & 15) << 5;    // 32 d's per block

    // --- LIF scan (MLP=16 load batch, then serial recurrence in regs) ---
    {
        int cc = tid;
        float xv[TT];
#pragma unroll
        for (int t = 0; t < TT; ++t)
            xv[t] = cond[(t * BB + b) * CC + cc];
        float v = 0.0f;
#pragma unroll
        for (int t = 0; t < TT; ++t) {
            v = v + (xv[t] - v) * 0.5f;              // charge (TAU=2)
            float s = (v >= 1.0f) ? 1.0f : 0.0f;     // fire
            s_sp[t][cc] = s;
            v = (1.0f - s) * v;                      // hard reset
        }
    }
    __syncthreads();

    // --- GEMM: params[t,b,d] = sum_c sp[t,c]*W[d,c] + bias[d] ---
    int dl = tid >> 3;                 // 0..31
    int tp = tid & 7;                  // 0..7 -> t pair
    int d  = dbase + dl;
    int t0 = tp * 2, t1 = t0 + 1;

    const float4* __restrict__ w4 = (const float4*)(Wm + (size_t)d * CC);
    const float4* __restrict__ s0 = (const float4*)&s_sp[t0][0];
    const float4* __restrict__ s1 = (const float4*)&s_sp[t1][0];

    float a0 = bias[d], a1 = a0;
#pragma unroll 8
    for (int k = 0; k < CC / 4; ++k) {
        float4 w = w4[k];
        float4 p = s0[k];
        float4 q = s1[k];
        a0 = fmaf(p.x, w.x, a0); a0 = fmaf(p.y, w.y, a0);
        a0 = fmaf(p.z, w.z, a0); a0 = fmaf(p.w, w.w, a0);
        a1 = fmaf(q.x, w.x, a1); a1 = fmaf(q.y, w.y, a1);
        a1 = fmaf(q.z, w.z, a1); a1 = fmaf(q.w, w.w, a1);
    }
    g_params[(t0 * BB + b) * DD + d] = a0;
    g_params[(t1 * BB + b) * DD + d] = a1;
}

// ---------------------------------------------------------------------------
// FiLM elementwise (the measured 77us / 6.3TB/s kernel, byte-identical).
// One tile per block: 8 consecutive channels, all 8 float4 loads hoisted
// (MLP=8). out = (1+gamma)*x + beta.
// ---------------------------------------------------------------------------
__global__ void __launch_bounds__(256) film_kernel(
    const float4* __restrict__ x, float4* __restrict__ out) {
    unsigned row0 = blockIdx.x * 8;
    unsigned tb   = row0 >> 8;
    unsigned c0   = row0 & (CC - 1);

    size_t base = (size_t)row0 * 256 + threadIdx.x;

    float4 v0 = x[base];
    float4 v1 = x[base + 256];
    float4 v2 = x[base + 512];
    float4 v3 = x[base + 768];
    float4 v4 = x[base + 1024];
    float4 v5 = x[base + 1280];
    float4 v6 = x[base + 1536];
    float4 v7 = x[base + 1792];

    const float4* __restrict__ p4 = (const float4*)(g_params + tb * DD + c0);
    float4 ga = p4[0];
    float4 gb = p4[1];
    float4 ba = p4[CC / 4];
    float4 bb = p4[CC / 4 + 1];

    float g0 = 1.0f + ga.x, g1 = 1.0f + ga.y, g2 = 1.0f + ga.z, g3 = 1.0f + ga.w;
    float g4 = 1.0f + gb.x, g5 = 1.0f + gb.y, g6 = 1.0f + gb.z, g7 = 1.0f + gb.w;

    float4 o;
    o.x = fmaf(g0, v0.x, ba.x); o.y = fmaf(g0, v0.y, ba.x);
    o.z = fmaf(g0, v0.z, ba.x); o.w = fmaf(g0, v0.w, ba.x);
    out[base] = o;
    o.x = fmaf(g1, v1.x, ba.y); o.y = fmaf(g1, v1.y, ba.y);
    o.z = fmaf(g1, v1.z, ba.y); o.w = fmaf(g1, v1.w, ba.y);
    out[base + 256] = o;
    o.x = fmaf(g2, v2.x, ba.z); o.y = fmaf(g2, v2.y, ba.z);
    o.z = fmaf(g2, v2.z, ba.z); o.w = fmaf(g2, v2.w, ba.z);
    out[base + 512] = o;
    o.x = fmaf(g3, v3.x, ba.w); o.y = fmaf(g3, v3.y, ba.w);
    o.z = fmaf(g3, v3.z, ba.w); o.w = fmaf(g3, v3.w, ba.w);
    out[base + 768] = o;
    o.x = fmaf(g4, v4.x, bb.x); o.y = fmaf(g4, v4.y, bb.x);
    o.z = fmaf(g4, v4.z, bb.x); o.w = fmaf(g4, v4.w, bb.x);
    out[base + 1024] = o;
    o.x = fmaf(g5, v5.x, bb.y); o.y = fmaf(g5, v5.y, bb.y);
    o.z = fmaf(g5, v5.z, bb.y); o.w = fmaf(g5, v5.w, bb.y);
    out[base + 1280] = o;
    o.x = fmaf(g6, v6.x, bb.z); o.y = fmaf(g6, v6.y, bb.z);
    o.z = fmaf(g6, v6.z, bb.z); o.w = fmaf(g6, v6.w, bb.z);
    out[base + 1536] = o;
    o.x = fmaf(g7, v7.x, bb.w); o.y = fmaf(g7, v7.y, bb.w);
    o.z = fmaf(g7, v7.z, bb.w); o.w = fmaf(g7, v7.w, bb.w);
    out[base + 1792] = o;
}

// ---------------------------------------------------------------------------
extern "C" void kernel_launch(void* const* d_in, const int* in_sizes, int n_in,
                              void* d_out, int out_size) {
    const float* x    = (const float*)d_in[0];   // [T,B,C,H,W]
    const float* cond = (const float*)d_in[1];   // [T,B,Cc]
    const float* Wm   = (const float*)d_in[2];   // [2C,Cc]
    const float* bias = (const float*)d_in[3];   // [2C]
    float* out = (float*)d_out;

    head_kernel<<<BB * 16, 256>>>(cond, Wm, bias);
    film_kernel<<<TT * BB * CC / 8, 256>>>((const float4*)x, (float4*)out);
}